// round 4
// baseline (speedup 1.0000x reference)
#include <cuda_runtime.h>
#include <cstdint>

// Problem constants
#define B_ 4
#define C_ 64
#define H_ 128
#define W_ 128
#define HW_ 16384
#define OCH_ 18
#define COUT_ 64
#define K2_ 9

#define VP 68   // V tile row pitch (words) — conflict-free A-frag LDS
#define WP 72   // W tile row pitch (words) — conflict-free B-frag LDS

// Scratch (device globals)
__device__ float g_offs[B_ * OCH_ * HW_];       // offset conv result
__device__ float g_xt[B_ * HW_ * C_];           // x transposed: [b][h][w][c]
__device__ uint32_t g_wt[K2_ * C_ * COUT_];     // w_deform tf32: [tap][c][o]

// ---- packed f32x2 helpers ----
__device__ __forceinline__ unsigned long long pk2(float a, float b) {
    unsigned long long r;
    asm("mov.b64 %0, {%1, %2};" : "=l"(r) : "f"(a), "f"(b));
    return r;
}
__device__ __forceinline__ unsigned long long fma2(unsigned long long a,
                                                   unsigned long long b,
                                                   unsigned long long c) {
    unsigned long long d;
    asm("fma.rn.f32x2 %0, %1, %2, %3;" : "=l"(d) : "l"(a), "l"(b), "l"(c));
    return d;
}
__device__ __forceinline__ float2 upk(unsigned long long a) {
    float2 f;
    asm("mov.b64 {%0, %1}, %2;" : "=f"(f.x), "=f"(f.y) : "l"(a));
    return f;
}
__device__ __forceinline__ uint32_t to_tf32(float f) {
    uint32_t r;
    asm("cvt.rna.tf32.f32 %0, %1;" : "=r"(r) : "f"(f));
    return r;
}

// warp-level tf32 MMA: D(16x8) += A(16x8) * B(8x8)
__device__ __forceinline__ void mma_tf32(float* d, uint32_t a0, uint32_t a1,
                                         uint32_t a2, uint32_t a3,
                                         uint32_t b0, uint32_t b1) {
    asm volatile(
        "mma.sync.aligned.m16n8k8.row.col.f32.tf32.tf32.f32 "
        "{%0,%1,%2,%3}, {%4,%5,%6,%7}, {%8,%9}, {%0,%1,%2,%3};"
        : "+f"(d[0]), "+f"(d[1]), "+f"(d[2]), "+f"(d[3])
        : "r"(a0), "r"(a1), "r"(a2), "r"(a3), "r"(b0), "r"(b1));
}

// ---------------------------------------------------------------------------
// Kernel: transpose w_deform [o][c][3][3] -> g_wt[tap][c][o] (tf32 bits)
// ---------------------------------------------------------------------------
__global__ void k_transpose_w(const float* __restrict__ wd) {
    int idx = blockIdx.x * 256 + threadIdx.x;
    if (idx >= K2_ * C_ * COUT_) return;
    int tap = idx >> 12;
    int r   = idx & 4095;
    int c   = r >> 6;
    int o   = r & 63;
    g_wt[idx] = to_tf32(wd[(o * C_ + c) * K2_ + tap]);
}

// ---------------------------------------------------------------------------
// Kernel: transpose x [b][c][h][w] -> g_xt[b][h][w][c]
// ---------------------------------------------------------------------------
__global__ __launch_bounds__(256) void k_transpose_x(const float* __restrict__ x) {
    __shared__ float tile[64 * 129];
    int bh = blockIdx.x;
    int b = bh >> 7, h = bh & 127;
    int t = threadIdx.x;
    const float* xb = x + ((size_t)b * C_ * H_ + h) * W_;
#pragma unroll
    for (int i = 0; i < 32; ++i) {
        int e = t + i * 256;
        int c = e >> 7, w = e & 127;
        tile[c * 129 + w] = xb[(size_t)c * HW_ + w];
    }
    __syncthreads();
    float* ob = g_xt + ((size_t)b * H_ + h) * W_ * C_;
#pragma unroll
    for (int i = 0; i < 32; ++i) {
        int e = t + i * 256;
        int w = e >> 6, c = e & 63;
        ob[w * C_ + c] = tile[c * 129 + w];
    }
}

// ---------------------------------------------------------------------------
// Kernel: offset conv (3x3, 64 -> 18, pad 1) with packed f32x2 FMAs.
// ---------------------------------------------------------------------------
__global__ __launch_bounds__(256) void k_offset_conv(
    const float* __restrict__ x, const float* __restrict__ w_offset) {
    __shared__ float ws[192 * 56];
    int t = threadIdx.x;
    for (int e = t; e < OCH_ * C_ * K2_; e += 256) {
        int och = e / (C_ * K2_);
        int r   = e % (C_ * K2_);
        int c   = r / K2_;
        int ky  = (r % K2_) / 3;
        int kx  = r % 3;
        ws[(c * 3 + ky) * 56 + kx * 18 + och] = w_offset[e];
    }
    __syncthreads();

    int idx = blockIdx.x * 256 + t;
    int b = idx >> 14, rem = idx & 16383;
    int h = rem >> 7,  w = rem & 127;

    unsigned long long acc2[9];
#pragma unroll
    for (int i = 0; i < 9; ++i) acc2[i] = 0ULL;

    const float* xb = x + (size_t)b * C_ * HW_;
    for (int ky = 0; ky < 3; ++ky) {
        int y = h - 1 + ky;
        bool rv = (y >= 0) && (y < H_);
        for (int c = 0; c < C_; ++c) {
            const float* xr = xb + ((size_t)c * H_ + y) * W_;
            float xv0 = (rv && w >= 1)   ? xr[w - 1] : 0.f;
            float xv1 = rv               ? xr[w]     : 0.f;
            float xv2 = (rv && w <= 126) ? xr[w + 1] : 0.f;

            const ulonglong2* wrow = (const ulonglong2*)(ws + (c * 3 + ky) * 56);
            unsigned long long wv2[28];
#pragma unroll
            for (int j = 0; j < 14; ++j) {
                ulonglong2 q = wrow[j];
                wv2[2 * j] = q.x; wv2[2 * j + 1] = q.y;
            }
            unsigned long long xp0 = pk2(xv0, xv0);
            unsigned long long xp1 = pk2(xv1, xv1);
            unsigned long long xp2 = pk2(xv2, xv2);
#pragma unroll
            for (int j = 0; j < 9; ++j) {
                acc2[j] = fma2(wv2[j],      xp0, acc2[j]);
                acc2[j] = fma2(wv2[9 + j],  xp1, acc2[j]);
                acc2[j] = fma2(wv2[18 + j], xp2, acc2[j]);
            }
        }
    }
#pragma unroll
    for (int j = 0; j < 9; ++j) {
        float2 r = upk(acc2[j]);
        g_offs[(((size_t)b * OCH_ + 2 * j)     * H_ + h) * W_ + w] = r.x;
        g_offs[(((size_t)b * OCH_ + 2 * j + 1) * H_ + h) * W_ + w] = r.y;
    }
}

// ---------------------------------------------------------------------------
// Kernel: main deform-conv via mma.sync tf32 (m16n8k8).
// One block per (b,h), 256 threads (8 warps). Per tap: gather bilinear V tile
// [128p x 64c] into smem (tf32), stage W tap tile [64c x 64o], then each warp
// does a 16x64 output slab: 8 kstep x 8 nblk mma, accumulating across taps.
// ---------------------------------------------------------------------------
__global__ __launch_bounds__(256) void k_deform_mma(float* __restrict__ out) {
    extern __shared__ uint32_t dsm[];
    uint32_t* vsm = dsm;                 // [128][VP]
    uint32_t* wsm = dsm + 128 * VP;      // [64][WP]

    int bh = blockIdx.x;
    int b = bh >> 7, h = bh & 127;
    int t = threadIdx.x;
    int wid = t >> 5, lane = t & 31;
    int g  = lane >> 2;     // 0..7
    int tg = lane & 3;      // 0..3
    int warp_m = wid * 16;

    // gather mapping
    int pa = t & 127;
    int qa = t >> 7;        // 0/1 -> channels qa*32 .. +31
    int c0 = qa * 32;

    const float* ob = g_offs + ((size_t)b * OCH_ * H_ + h) * W_;
    const float* xt = g_xt + (size_t)b * HW_ * C_;

    float acc[8][4];
#pragma unroll
    for (int i = 0; i < 8; ++i)
#pragma unroll
        for (int j = 0; j < 4; ++j) acc[i][j] = 0.f;

    for (int tap = 0; tap < K2_; ++tap) {
        int ky = tap / 3, kx = tap % 3;

        // ---- stage W tap tile (tf32 copy, coalesced) ----
        {
            const uint4* src = (const uint4*)(g_wt + tap * 4096);
#pragma unroll
            for (int i = t; i < 1024; i += 256) {
                int e = i * 4;
                int c = e >> 6, o = e & 63;
                *(uint4*)(wsm + c * WP + o) = src[i];
            }
        }

        // ---- gather V tile (bilinear from NHWC x) ----
        {
            float dy = ob[(size_t)(2 * tap)     * HW_ + pa];
            float dx = ob[(size_t)(2 * tap + 1) * HW_ + pa];
            float py = (float)(h - 1 + ky) + dy;
            float px = (float)(pa - 1 + kx) + dx;
            float y0f = floorf(py), x0f = floorf(px);
            float ly = py - y0f, lx = px - x0f;
            int y0 = (int)y0f, x0 = (int)x0f;
            int y1 = y0 + 1,   x1 = x0 + 1;

            bool vy0 = (y0 >= 0) && (y0 < H_);
            bool vy1 = (y1 >= 0) && (y1 < H_);
            bool vx0 = (x0 >= 0) && (x0 < W_);
            bool vx1 = (x1 >= 0) && (x1 < W_);

            float w00 = (1.f - ly) * (1.f - lx) * ((vy0 && vx0) ? 1.f : 0.f);
            float w01 = (1.f - ly) * lx         * ((vy0 && vx1) ? 1.f : 0.f);
            float w10 = ly * (1.f - lx)         * ((vy1 && vx0) ? 1.f : 0.f);
            float w11 = ly * lx                 * ((vy1 && vx1) ? 1.f : 0.f);

            int y0c = min(max(y0, 0), H_ - 1);
            int y1c = min(max(y1, 0), H_ - 1);
            int x0c = min(max(x0, 0), W_ - 1);
            int x1c = min(max(x1, 0), W_ - 1);

            const float* p00 = xt + (size_t)(y0c * W_ + x0c) * C_ + c0;
            const float* p01 = xt + (size_t)(y0c * W_ + x1c) * C_ + c0;
            const float* p10 = xt + (size_t)(y1c * W_ + x0c) * C_ + c0;
            const float* p11 = xt + (size_t)(y1c * W_ + x1c) * C_ + c0;

            unsigned long long w00p = pk2(w00, w00);
            unsigned long long w01p = pk2(w01, w01);
            unsigned long long w10p = pk2(w10, w10);
            unsigned long long w11p = pk2(w11, w11);

            uint32_t* vrow = vsm + pa * VP + c0;
#pragma unroll
            for (int gi = 0; gi < 8; ++gi) {
                ulonglong2 a4 = *(const ulonglong2*)(p00 + gi * 4);
                ulonglong2 b4 = *(const ulonglong2*)(p01 + gi * 4);
                ulonglong2 c4 = *(const ulonglong2*)(p10 + gi * 4);
                ulonglong2 d4 = *(const ulonglong2*)(p11 + gi * 4);
                unsigned long long lo = fma2(w00p, a4.x,
                                        fma2(w01p, b4.x,
                                        fma2(w10p, c4.x,
                                        fma2(w11p, d4.x, 0ULL))));
                unsigned long long hi = fma2(w00p, a4.y,
                                        fma2(w01p, b4.y,
                                        fma2(w10p, c4.y,
                                        fma2(w11p, d4.y, 0ULL))));
                float2 flo = upk(lo), fhi = upk(hi);
                uint4 u;
                u.x = to_tf32(flo.x); u.y = to_tf32(flo.y);
                u.z = to_tf32(fhi.x); u.w = to_tf32(fhi.y);
                *(uint4*)(vrow + gi * 4) = u;
            }
        }

        __syncthreads();

        // ---- mma phase ----
#pragma unroll
        for (int ks = 0; ks < 8; ++ks) {
            int k0 = ks * 8;
            uint32_t a0 = vsm[(warp_m + g)     * VP + k0 + tg];
            uint32_t a1 = vsm[(warp_m + g + 8) * VP + k0 + tg];
            uint32_t a2 = vsm[(warp_m + g)     * VP + k0 + tg + 4];
            uint32_t a3 = vsm[(warp_m + g + 8) * VP + k0 + tg + 4];
#pragma unroll
            for (int nb = 0; nb < 8; ++nb) {
                uint32_t b0 = wsm[(k0 + tg)     * WP + nb * 8 + g];
                uint32_t b1 = wsm[(k0 + tg + 4) * WP + nb * 8 + g];
                mma_tf32(acc[nb], a0, a1, a2, a3, b0, b1);
            }
        }

        __syncthreads();
    }

    // ---- epilogue: D rows (warp_m+g, warp_m+g+8), cols o = nb*8 + 2tg,+1 ----
    int p = warp_m + g;
    float* outb = out + (((size_t)b * COUT_) * H_ + h) * W_;
#pragma unroll
    for (int nb = 0; nb < 8; ++nb) {
        int o = nb * 8 + tg * 2;
        outb[(size_t)o       * HW_ + p]     = acc[nb][0];
        outb[(size_t)(o + 1) * HW_ + p]     = acc[nb][1];
        outb[(size_t)o       * HW_ + p + 8] = acc[nb][2];
        outb[(size_t)(o + 1) * HW_ + p + 8] = acc[nb][3];
    }
}

#define DSM_BYTES ((128 * VP + 64 * WP) * 4)

// ---------------------------------------------------------------------------
extern "C" void kernel_launch(void* const* d_in, const int* in_sizes, int n_in,
                              void* d_out, int out_size) {
    const float* x        = (const float*)d_in[0];
    const float* w_offset = (const float*)d_in[1];
    const float* w_deform = (const float*)d_in[2];
    float* out = (float*)d_out;

    cudaFuncSetAttribute(k_deform_mma,
                         cudaFuncAttributeMaxDynamicSharedMemorySize, DSM_BYTES);

    k_transpose_w<<<(K2_ * C_ * COUT_ + 255) / 256, 256>>>(w_deform);
    k_transpose_x<<<B_ * H_, 256>>>(x);
    k_offset_conv<<<(B_ * HW_) / 256, 256>>>(x, w_offset);
    k_deform_mma<<<B_ * H_, 256, DSM_BYTES>>>(out);
}

// round 5
// speedup vs baseline: 1.4940x; 1.4940x over previous
#include <cuda_runtime.h>
#include <cstdint>

// Problem constants
#define B_ 4
#define C_ 64
#define H_ 128
#define W_ 128
#define HW_ 16384
#define OCH_ 18
#define COUT_ 64
#define K2_ 9

#define VP 68   // V tile row pitch (words) — conflict-free A-frag LDS
#define WP 72   // W tile row pitch (words) — conflict-free B-frag LDS

// Scratch (device globals)
__device__ float g_offs[B_ * OCH_ * HW_];       // offset conv result
__device__ float g_xt[B_ * HW_ * C_];           // x transposed: [b][h][w][c]
__device__ uint32_t g_wt[K2_ * C_ * COUT_];     // w_deform tf32: [tap][c][o]

// ---- packed f32x2 helpers ----
__device__ __forceinline__ unsigned long long pk2(float a, float b) {
    unsigned long long r;
    asm("mov.b64 %0, {%1, %2};" : "=l"(r) : "f"(a), "f"(b));
    return r;
}
__device__ __forceinline__ unsigned long long fma2(unsigned long long a,
                                                   unsigned long long b,
                                                   unsigned long long c) {
    unsigned long long d;
    asm("fma.rn.f32x2 %0, %1, %2, %3;" : "=l"(d) : "l"(a), "l"(b), "l"(c));
    return d;
}
__device__ __forceinline__ float2 upk(unsigned long long a) {
    float2 f;
    asm("mov.b64 {%0, %1}, %2;" : "=f"(f.x), "=f"(f.y) : "l"(a));
    return f;
}
__device__ __forceinline__ uint32_t to_tf32(float f) {
    uint32_t r;
    asm("cvt.rna.tf32.f32 %0, %1;" : "=r"(r) : "f"(f));
    return r;
}

// warp-level tf32 MMA: D(16x8) += A(16x8) * B(8x8)
__device__ __forceinline__ void mma_tf32(float* d, uint32_t a0, uint32_t a1,
                                         uint32_t a2, uint32_t a3,
                                         uint32_t b0, uint32_t b1) {
    asm volatile(
        "mma.sync.aligned.m16n8k8.row.col.f32.tf32.tf32.f32 "
        "{%0,%1,%2,%3}, {%4,%5,%6,%7}, {%8,%9}, {%0,%1,%2,%3};"
        : "+f"(d[0]), "+f"(d[1]), "+f"(d[2]), "+f"(d[3])
        : "r"(a0), "r"(a1), "r"(a2), "r"(a3), "r"(b0), "r"(b1));
}

// ---------------------------------------------------------------------------
// Kernel: transpose w_deform [o][c][3][3] -> g_wt[tap][c][o] (tf32 bits)
// ---------------------------------------------------------------------------
__global__ void k_transpose_w(const float* __restrict__ wd) {
    int idx = blockIdx.x * 256 + threadIdx.x;
    if (idx >= K2_ * C_ * COUT_) return;
    int tap = idx >> 12;
    int r   = idx & 4095;
    int c   = r >> 6;
    int o   = r & 63;
    g_wt[idx] = to_tf32(wd[(o * C_ + c) * K2_ + tap]);
}

// ---------------------------------------------------------------------------
// Kernel: transpose x [b][c][h][w] -> g_xt[b][h][w][c]
// ---------------------------------------------------------------------------
__global__ __launch_bounds__(256) void k_transpose_x(const float* __restrict__ x) {
    __shared__ float tile[64 * 129];
    int bh = blockIdx.x;
    int b = bh >> 7, h = bh & 127;
    int t = threadIdx.x;
    const float* xb = x + ((size_t)b * C_ * H_ + h) * W_;
#pragma unroll
    for (int i = 0; i < 32; ++i) {
        int e = t + i * 256;
        int c = e >> 7, w = e & 127;
        tile[c * 129 + w] = xb[(size_t)c * HW_ + w];
    }
    __syncthreads();
    float* ob = g_xt + ((size_t)b * H_ + h) * W_ * C_;
#pragma unroll
    for (int i = 0; i < 32; ++i) {
        int e = t + i * 256;
        int w = e >> 6, c = e & 63;
        ob[w * C_ + c] = tile[c * 129 + w];
    }
}

// ---------------------------------------------------------------------------
// Kernel: offset conv (3x3, 64 -> 18, pad 1). TWO adjacent pixels per thread
// so each broadcast weight load feeds 2x the FMAs.
// ---------------------------------------------------------------------------
__global__ __launch_bounds__(256) void k_offset_conv(
    const float* __restrict__ x, const float* __restrict__ w_offset) {
    __shared__ float ws[192 * 56];
    int t = threadIdx.x;
    for (int e = t; e < OCH_ * C_ * K2_; e += 256) {
        int och = e / (C_ * K2_);
        int r   = e % (C_ * K2_);
        int c   = r / K2_;
        int ky  = (r % K2_) / 3;
        int kx  = r % 3;
        ws[(c * 3 + ky) * 56 + kx * 18 + och] = w_offset[e];
    }
    __syncthreads();

    int idx = blockIdx.x * 256 + t;        // pixel-pair index
    int b   = idx >> 13;                   // 8192 pairs per image
    int rem = idx & 8191;
    int h   = rem >> 6;
    int wp  = (rem & 63) << 1;             // pixels wp, wp+1

    unsigned long long accA[9], accB[9];
#pragma unroll
    for (int i = 0; i < 9; ++i) { accA[i] = 0ULL; accB[i] = 0ULL; }

    const float* xb = x + (size_t)b * C_ * HW_;
    for (int ky = 0; ky < 3; ++ky) {
        int y = h - 1 + ky;
        bool rv = (y >= 0) && (y < H_);
        for (int c = 0; c < C_; ++c) {
            const float* xr = xb + ((size_t)c * H_ + y) * W_;
            float xm1 = (rv && wp >= 1)   ? xr[wp - 1] : 0.f;
            float x0v = rv                ? xr[wp]     : 0.f;
            float x1v = rv                ? xr[wp + 1] : 0.f;
            float x2v = (rv && wp <= 125) ? xr[wp + 2] : 0.f;

            const ulonglong2* wrow = (const ulonglong2*)(ws + (c * 3 + ky) * 56);
            unsigned long long wv2[28];
#pragma unroll
            for (int j = 0; j < 14; ++j) {
                ulonglong2 q = wrow[j];
                wv2[2 * j] = q.x; wv2[2 * j + 1] = q.y;
            }
            unsigned long long pm1 = pk2(xm1, xm1);
            unsigned long long p0  = pk2(x0v, x0v);
            unsigned long long p1  = pk2(x1v, x1v);
            unsigned long long p2  = pk2(x2v, x2v);
#pragma unroll
            for (int j = 0; j < 9; ++j) {
                accA[j] = fma2(wv2[j],      pm1, accA[j]);
                accA[j] = fma2(wv2[9 + j],  p0,  accA[j]);
                accA[j] = fma2(wv2[18 + j], p1,  accA[j]);
                accB[j] = fma2(wv2[j],      p0,  accB[j]);
                accB[j] = fma2(wv2[9 + j],  p1,  accB[j]);
                accB[j] = fma2(wv2[18 + j], p2,  accB[j]);
            }
        }
    }
#pragma unroll
    for (int j = 0; j < 9; ++j) {
        float2 ra = upk(accA[j]);
        float2 rb = upk(accB[j]);
        float* o0 = g_offs + (((size_t)b * OCH_ + 2 * j)     * H_ + h) * W_ + wp;
        float* o1 = g_offs + (((size_t)b * OCH_ + 2 * j + 1) * H_ + h) * W_ + wp;
        float2 v0; v0.x = ra.x; v0.y = rb.x;
        float2 v1; v1.x = ra.y; v1.y = rb.y;
        *(float2*)o0 = v0;
        *(float2*)o1 = v1;
    }
}

// ---------------------------------------------------------------------------
// Kernel: main deform-conv via mma.sync tf32 (m16n8k8).
// One block per (b,h), 256 threads (8 warps).
// Per tap: (1) stage W tile + precompute per-pixel bilinear params,
// (2) COALESCED gather: 16 lanes load 64 channels of one pixel's corners,
// (3) mma: warp does 16x64 output slab, accumulate across taps.
// ---------------------------------------------------------------------------
__global__ __launch_bounds__(256) void k_deform_mma(float* __restrict__ out) {
    extern __shared__ uint32_t dsm[];
    uint32_t* vsm = dsm;                          // [128][VP]
    uint32_t* wsm = dsm + 128 * VP;               // [64][WP]
    float4*   pw  = (float4*)(dsm + 128 * VP + 64 * WP);  // [128] bilinear wgts
    int4*     pi  = (int4*)(pw + 128);                    // [128] corner idx

    int bh = blockIdx.x;
    int b = bh >> 7, h = bh & 127;
    int t = threadIdx.x;
    int wid = t >> 5, lane = t & 31;
    int g  = lane >> 2;     // 0..7
    int tg = lane & 3;      // 0..3
    int warp_m = wid * 16;

    // gather mapping: warp handles 2 pixels/pass, 16 lanes = 64 channels
    int half = lane >> 4;          // 0/1 -> pixel select
    int cs   = (lane & 15) << 2;   // channel segment (4 floats)

    const float* ob = g_offs + ((size_t)b * OCH_ * H_ + h) * W_;
    const float* xt = g_xt + (size_t)b * HW_ * C_;

    float acc[8][4];
#pragma unroll
    for (int i = 0; i < 8; ++i)
#pragma unroll
        for (int j = 0; j < 4; ++j) acc[i][j] = 0.f;

    for (int tap = 0; tap < K2_; ++tap) {
        int ky = tap / 3, kx = tap % 3;

        // ---- stage W tap tile (tf32 copy, coalesced) ----
        {
            const uint4* src = (const uint4*)(g_wt + tap * 4096);
#pragma unroll
            for (int i = t; i < 1024; i += 256) {
                int e = i * 4;
                int c = e >> 6, o = e & 63;
                *(uint4*)(wsm + c * WP + o) = src[i];
            }
        }

        // ---- per-pixel bilinear params (threads 0..127) ----
        if (t < 128) {
            int px = t;
            float dy = ob[(size_t)(2 * tap)     * HW_ + px];
            float dx = ob[(size_t)(2 * tap + 1) * HW_ + px];
            float py = (float)(h - 1 + ky) + dy;
            float pxf = (float)(px - 1 + kx) + dx;
            float y0f = floorf(py), x0f = floorf(pxf);
            float ly = py - y0f, lx = pxf - x0f;
            int y0 = (int)y0f, x0 = (int)x0f;
            int y1 = y0 + 1,   x1 = x0 + 1;

            bool vy0 = (y0 >= 0) && (y0 < H_);
            bool vy1 = (y1 >= 0) && (y1 < H_);
            bool vx0 = (x0 >= 0) && (x0 < W_);
            bool vx1 = (x1 >= 0) && (x1 < W_);

            float4 wg;
            wg.x = (1.f - ly) * (1.f - lx) * ((vy0 && vx0) ? 1.f : 0.f);
            wg.y = (1.f - ly) * lx         * ((vy0 && vx1) ? 1.f : 0.f);
            wg.z = ly * (1.f - lx)         * ((vy1 && vx0) ? 1.f : 0.f);
            wg.w = ly * lx                 * ((vy1 && vx1) ? 1.f : 0.f);

            int y0c = min(max(y0, 0), H_ - 1);
            int y1c = min(max(y1, 0), H_ - 1);
            int x0c = min(max(x0, 0), W_ - 1);
            int x1c = min(max(x1, 0), W_ - 1);

            int4 ix;
            ix.x = y0c * W_ + x0c;
            ix.y = y0c * W_ + x1c;
            ix.z = y1c * W_ + x0c;
            ix.w = y1c * W_ + x1c;
            pw[px] = wg;
            pi[px] = ix;
        }
        __syncthreads();

        // ---- coalesced gather: 8 passes x (2 pixels/warp) ----
#pragma unroll
        for (int pass = 0; pass < 8; ++pass) {
            int px = pass * 16 + (wid << 1) + half;
            float4 wg = pw[px];
            int4   ix = pi[px];

            ulonglong2 a4 = *(const ulonglong2*)(xt + (size_t)ix.x * C_ + cs);
            ulonglong2 b4 = *(const ulonglong2*)(xt + (size_t)ix.y * C_ + cs);
            ulonglong2 c4 = *(const ulonglong2*)(xt + (size_t)ix.z * C_ + cs);
            ulonglong2 d4 = *(const ulonglong2*)(xt + (size_t)ix.w * C_ + cs);

            unsigned long long w00p = pk2(wg.x, wg.x);
            unsigned long long w01p = pk2(wg.y, wg.y);
            unsigned long long w10p = pk2(wg.z, wg.z);
            unsigned long long w11p = pk2(wg.w, wg.w);

            unsigned long long lo = fma2(w00p, a4.x,
                                    fma2(w01p, b4.x,
                                    fma2(w10p, c4.x,
                                    fma2(w11p, d4.x, 0ULL))));
            unsigned long long hi = fma2(w00p, a4.y,
                                    fma2(w01p, b4.y,
                                    fma2(w10p, c4.y,
                                    fma2(w11p, d4.y, 0ULL))));
            float2 flo = upk(lo), fhi = upk(hi);
            uint4 u;
            u.x = to_tf32(flo.x); u.y = to_tf32(flo.y);
            u.z = to_tf32(fhi.x); u.w = to_tf32(fhi.y);
            *(uint4*)(vsm + px * VP + cs) = u;
        }

        __syncthreads();

        // ---- mma phase ----
#pragma unroll
        for (int ks = 0; ks < 8; ++ks) {
            int k0 = ks * 8;
            uint32_t a0 = vsm[(warp_m + g)     * VP + k0 + tg];
            uint32_t a1 = vsm[(warp_m + g + 8) * VP + k0 + tg];
            uint32_t a2 = vsm[(warp_m + g)     * VP + k0 + tg + 4];
            uint32_t a3 = vsm[(warp_m + g + 8) * VP + k0 + tg + 4];
#pragma unroll
            for (int nb = 0; nb < 8; ++nb) {
                uint32_t b0 = wsm[(k0 + tg)     * WP + nb * 8 + g];
                uint32_t b1 = wsm[(k0 + tg + 4) * WP + nb * 8 + g];
                mma_tf32(acc[nb], a0, a1, a2, a3, b0, b1);
            }
        }

        __syncthreads();
    }

    // ---- epilogue: D rows (warp_m+g, warp_m+g+8), cols o = nb*8 + 2tg,+1 ----
    int p = warp_m + g;
    float* outb = out + (((size_t)b * COUT_) * H_ + h) * W_;
#pragma unroll
    for (int nb = 0; nb < 8; ++nb) {
        int o = nb * 8 + tg * 2;
        outb[(size_t)o       * HW_ + p]     = acc[nb][0];
        outb[(size_t)(o + 1) * HW_ + p]     = acc[nb][1];
        outb[(size_t)o       * HW_ + p + 8] = acc[nb][2];
        outb[(size_t)(o + 1) * HW_ + p + 8] = acc[nb][3];
    }
}

#define DSM_BYTES (((128 * VP + 64 * WP) * 4) + 128 * 16 * 2)

// ---------------------------------------------------------------------------
extern "C" void kernel_launch(void* const* d_in, const int* in_sizes, int n_in,
                              void* d_out, int out_size) {
    const float* x        = (const float*)d_in[0];
    const float* w_offset = (const float*)d_in[1];
    const float* w_deform = (const float*)d_in[2];
    float* out = (float*)d_out;

    cudaFuncSetAttribute(k_deform_mma,
                         cudaFuncAttributeMaxDynamicSharedMemorySize, DSM_BYTES);

    k_transpose_w<<<(K2_ * C_ * COUT_ + 255) / 256, 256>>>(w_deform);
    k_transpose_x<<<B_ * H_, 256>>>(x);
    k_offset_conv<<<(B_ * HW_ / 2) / 256, 256>>>(x, w_offset);
    k_deform_mma<<<B_ * H_, 256, DSM_BYTES>>>(out);
}

// round 6
// speedup vs baseline: 2.0504x; 1.3724x over previous
#include <cuda_runtime.h>
#include <cstdint>

// Problem constants
#define B_ 4
#define C_ 64
#define H_ 128
#define W_ 128
#define HW_ 16384
#define OCH_ 18
#define COUT_ 64
#define K2_ 9

#define VP 68   // V tile row pitch (words) — conflict-free A-frag LDS
#define WP 72   // W tile row pitch (words) — conflict-free B-frag LDS

// Scratch (device globals)
__device__ float g_offs[B_ * OCH_ * HW_];        // offset conv result
__device__ float g_xt[B_ * HW_ * C_];            // x transposed: [b][h][w][c]
__device__ uint32_t g_wt[K2_ * C_ * COUT_];      // w_deform tf32: [tap][c][o]
__device__ uint32_t g_wo[3 * 192 * 24];          // w_offset tf32: [ky][kx*64+c][och24]

// ---- packed f32x2 helpers ----
__device__ __forceinline__ unsigned long long pk2(float a, float b) {
    unsigned long long r;
    asm("mov.b64 %0, {%1, %2};" : "=l"(r) : "f"(a), "f"(b));
    return r;
}
__device__ __forceinline__ unsigned long long fma2(unsigned long long a,
                                                   unsigned long long b,
                                                   unsigned long long c) {
    unsigned long long d;
    asm("fma.rn.f32x2 %0, %1, %2, %3;" : "=l"(d) : "l"(a), "l"(b), "l"(c));
    return d;
}
__device__ __forceinline__ float2 upk(unsigned long long a) {
    float2 f;
    asm("mov.b64 {%0, %1}, %2;" : "=f"(f.x), "=f"(f.y) : "l"(a));
    return f;
}
__device__ __forceinline__ uint32_t to_tf32(float f) {
    uint32_t r;
    asm("cvt.rna.tf32.f32 %0, %1;" : "=r"(r) : "f"(f));
    return r;
}

// warp-level tf32 MMA: D(16x8) += A(16x8) * B(8x8)
__device__ __forceinline__ void mma_tf32(float* d, uint32_t a0, uint32_t a1,
                                         uint32_t a2, uint32_t a3,
                                         uint32_t b0, uint32_t b1) {
    asm volatile(
        "mma.sync.aligned.m16n8k8.row.col.f32.tf32.tf32.f32 "
        "{%0,%1,%2,%3}, {%4,%5,%6,%7}, {%8,%9}, {%0,%1,%2,%3};"
        : "+f"(d[0]), "+f"(d[1]), "+f"(d[2]), "+f"(d[3])
        : "r"(a0), "r"(a1), "r"(a2), "r"(a3), "r"(b0), "r"(b1));
}

// ---------------------------------------------------------------------------
// transpose w_deform [o][c][3][3] -> g_wt[tap][c][o] (tf32 bits)
// ---------------------------------------------------------------------------
__global__ void k_transpose_w(const float* __restrict__ wd) {
    int idx = blockIdx.x * 256 + threadIdx.x;
    if (idx >= K2_ * C_ * COUT_) return;
    int tap = idx >> 12;
    int r   = idx & 4095;
    int c   = r >> 6;
    int o   = r & 63;
    g_wt[idx] = to_tf32(wd[(o * C_ + c) * K2_ + tap]);
}

// ---------------------------------------------------------------------------
// transpose w_offset [och][c][3][3] -> g_wo[ky][kx*64+c][n] (n = och padded 24)
// ---------------------------------------------------------------------------
__global__ void k_transpose_wo(const float* __restrict__ wo) {
    int idx = blockIdx.x * 256 + threadIdx.x;
    if (idx >= 3 * 192 * 24) return;
    int ky = idx / (192 * 24);
    int r  = idx % (192 * 24);
    int k  = r / 24;
    int n  = r % 24;
    int kx = k >> 6;
    int c  = k & 63;
    float v = (n < OCH_) ? wo[((size_t)n * C_ + c) * K2_ + ky * 3 + kx] : 0.f;
    g_wo[idx] = to_tf32(v);
}

// ---------------------------------------------------------------------------
// transpose x [b][c][h][w] -> g_xt[b][h][w][c]
// ---------------------------------------------------------------------------
__global__ __launch_bounds__(256) void k_transpose_x(const float* __restrict__ x) {
    __shared__ float tile[64 * 129];
    int bh = blockIdx.x;
    int b = bh >> 7, h = bh & 127;
    int t = threadIdx.x;
    const float* xb = x + ((size_t)b * C_ * H_ + h) * W_;
#pragma unroll
    for (int i = 0; i < 32; ++i) {
        int e = t + i * 256;
        int c = e >> 7, w = e & 127;
        tile[c * 129 + w] = xb[(size_t)c * HW_ + w];
    }
    __syncthreads();
    float* ob = g_xt + ((size_t)b * H_ + h) * W_ * C_;
#pragma unroll
    for (int i = 0; i < 32; ++i) {
        int e = t + i * 256;
        int w = e >> 6, c = e & 63;
        ob[w * C_ + c] = tile[c * 129 + w];
    }
}

// ---------------------------------------------------------------------------
// Offset conv as tf32 mma: out[128p x 18och] = sum_ky A_ky[128 x 192] x B_ky.
// One block per (b,h), 256 threads, 8 warps (each M=16 slab, N=24).
// A_ky[p][kx*64+c] = x[y=h-1+ky][p-1+kx][c], staged from NHWC g_xt as tf32.
// ---------------------------------------------------------------------------
#define XSP 68
#define OSM_WORDS (130 * XSP + 192 * 24)
__global__ __launch_bounds__(256) void k_offset_mma(float* __restrict__ dummy) {
    extern __shared__ uint32_t osm[];
    uint32_t* xs  = osm;             // [130][XSP]
    uint32_t* wos = osm + 130 * XSP; // [192][24]

    int bh = blockIdx.x;
    int b = bh >> 7, h = bh & 127;
    int t = threadIdx.x;
    int wid = t >> 5, lane = t & 31;
    int g  = lane >> 2;
    int tg = lane & 3;
    int warp_m = wid * 16;

    const float* xt = g_xt + (size_t)b * HW_ * C_;

    float acc[3][4];
#pragma unroll
    for (int i = 0; i < 3; ++i)
#pragma unroll
        for (int j = 0; j < 4; ++j) acc[i][j] = 0.f;

    for (int ky = 0; ky < 3; ++ky) {
        int y = h - 1 + ky;
        bool yv = (y >= 0) && (y < H_);

        // stage x row slab: xs[j][c] = x[y][j-1][c], j in 0..129
        for (int idx = t; idx < 130 * 64; idx += 256) {
            int j = idx >> 6, c = idx & 63;
            float v = 0.f;
            if (yv && j >= 1 && j <= 128)
                v = xt[((size_t)y * W_ + (j - 1)) * C_ + c];
            xs[j * XSP + c] = to_tf32(v);
        }
        // stage W_ky
        for (int idx = t; idx < 192 * 24; idx += 256)
            wos[idx] = g_wo[ky * 192 * 24 + idx];
        __syncthreads();

#pragma unroll
        for (int ks = 0; ks < 24; ++ks) {
            int k0 = ks * 8;
            int kx = k0 >> 6;
            int c0 = k0 & 63;
            uint32_t a0 = xs[(warp_m + g + kx)     * XSP + c0 + tg];
            uint32_t a1 = xs[(warp_m + g + 8 + kx) * XSP + c0 + tg];
            uint32_t a2 = xs[(warp_m + g + kx)     * XSP + c0 + tg + 4];
            uint32_t a3 = xs[(warp_m + g + 8 + kx) * XSP + c0 + tg + 4];
#pragma unroll
            for (int nb = 0; nb < 3; ++nb) {
                uint32_t b0 = wos[(k0 + tg)     * 24 + nb * 8 + g];
                uint32_t b1 = wos[(k0 + tg + 4) * 24 + nb * 8 + g];
                mma_tf32(acc[nb], a0, a1, a2, a3, b0, b1);
            }
        }
        __syncthreads();
    }

    // epilogue: rows (warp_m+g, +8), cols och = nb*8 + 2tg (+1); och<18 only
    int p = warp_m + g;
    float* ofb = g_offs + ((size_t)b * OCH_ * H_ + h) * W_;
#pragma unroll
    for (int nb = 0; nb < 3; ++nb) {
        int och = nb * 8 + tg * 2;
        if (och < OCH_) {
            ofb[(size_t)och * HW_ + p]     = acc[nb][0];
            ofb[(size_t)och * HW_ + p + 8] = acc[nb][2];
        }
        if (och + 1 < OCH_) {
            ofb[(size_t)(och + 1) * HW_ + p]     = acc[nb][1];
            ofb[(size_t)(och + 1) * HW_ + p + 8] = acc[nb][3];
        }
    }
}

// ---------------------------------------------------------------------------
// Main deform-conv: tf32 mma, single-barrier software pipeline.
// iter i: stage W(i), params(i+1), gather(i) -- interleaved with mma(i-1).
// All cross-iteration buffers (V, W, params) double-buffered.
// ---------------------------------------------------------------------------
#define VW 8704                 // V buffer words (128*68)
#define WW 4608                 // W buffer words (64*72)
#define PW_OFF (2 * VW + 2 * WW)        // 26624 words
#define PI_OFF (PW_OFF + 2 * 128 * 4)   // +1024 words
#define DSM_WORDS (PI_OFF + 2 * 128 * 4)
#define DSM_BYTES (DSM_WORDS * 4)       // 114688

__global__ __launch_bounds__(256, 2) void k_deform_mma(float* __restrict__ out) {
    extern __shared__ uint32_t dsm[];
    float4* pwb = (float4*)(dsm + PW_OFF);
    int4*   pib = (int4*)(dsm + PI_OFF);

    int bh = blockIdx.x;
    int b = bh >> 7, h = bh & 127;
    int t = threadIdx.x;
    int wid = t >> 5, lane = t & 31;
    int g  = lane >> 2;
    int tg = lane & 3;
    int warp_m = wid * 16;

    int half = lane >> 4;          // gather: pixel select within warp pair
    int cs   = (lane & 15) << 2;   // channel segment (4 floats)

    const float* ob = g_offs + ((size_t)b * OCH_ * H_ + h) * W_;
    const float* xt = g_xt + (size_t)b * HW_ * C_;

    float acc[8][4];
#pragma unroll
    for (int i = 0; i < 8; ++i)
#pragma unroll
        for (int j = 0; j < 4; ++j) acc[i][j] = 0.f;

    // ---- params(0) prologue ----
    if (t < 128) {
        int px = t;
        float dy = ob[0 * HW_ + px];
        float dx = ob[1 * HW_ + px];
        float py = (float)(h - 1) + dy;
        float pxf = (float)(px - 1) + dx;
        float y0f = floorf(py), x0f = floorf(pxf);
        float ly = py - y0f, lx = pxf - x0f;
        int y0 = (int)y0f, x0 = (int)x0f;
        int y1 = y0 + 1,   x1 = x0 + 1;
        bool vy0 = (y0 >= 0) && (y0 < H_), vy1 = (y1 >= 0) && (y1 < H_);
        bool vx0 = (x0 >= 0) && (x0 < W_), vx1 = (x1 >= 0) && (x1 < W_);
        float4 wg;
        wg.x = (1.f - ly) * (1.f - lx) * ((vy0 && vx0) ? 1.f : 0.f);
        wg.y = (1.f - ly) * lx         * ((vy0 && vx1) ? 1.f : 0.f);
        wg.z = ly * (1.f - lx)         * ((vy1 && vx0) ? 1.f : 0.f);
        wg.w = ly * lx                 * ((vy1 && vx1) ? 1.f : 0.f);
        int y0c = min(max(y0, 0), H_ - 1), y1c = min(max(y1, 0), H_ - 1);
        int x0c = min(max(x0, 0), W_ - 1), x1c = min(max(x1, 0), W_ - 1);
        int4 ix;
        ix.x = y0c * W_ + x0c; ix.y = y0c * W_ + x1c;
        ix.z = y1c * W_ + x0c; ix.w = y1c * W_ + x1c;
        pwb[px] = wg;
        pib[px] = ix;
    }
    __syncthreads();

    for (int it = 0; it < 10; ++it) {
        int cur = it & 1, prv = cur ^ 1;
        uint32_t* vcur = dsm + cur * VW;
        uint32_t* vprv = dsm + prv * VW;
        uint32_t* wcur = dsm + 2 * VW + cur * WW;
        uint32_t* wprv = dsm + 2 * VW + prv * WW;

        if (it < 9) {
            // stage W(it)
            const uint4* src = (const uint4*)(g_wt + it * 4096);
#pragma unroll
            for (int i = t; i < 1024; i += 256) {
                int e = i * 4;
                int c = e >> 6, o = e & 63;
                *(uint4*)(wcur + c * WP + o) = src[i];
            }
            // params(it+1) into prv param buffer
            if (it < 8 && t < 128) {
                int tap = it + 1;
                int ky = tap / 3, kx = tap % 3;
                int px = t;
                float dy = ob[(size_t)(2 * tap)     * HW_ + px];
                float dx = ob[(size_t)(2 * tap + 1) * HW_ + px];
                float py = (float)(h - 1 + ky) + dy;
                float pxf = (float)(px - 1 + kx) + dx;
                float y0f = floorf(py), x0f = floorf(pxf);
                float ly = py - y0f, lx = pxf - x0f;
                int y0 = (int)y0f, x0 = (int)x0f;
                int y1 = y0 + 1,   x1 = x0 + 1;
                bool vy0 = (y0 >= 0) && (y0 < H_), vy1 = (y1 >= 0) && (y1 < H_);
                bool vx0 = (x0 >= 0) && (x0 < W_), vx1 = (x1 >= 0) && (x1 < W_);
                float4 wg;
                wg.x = (1.f - ly) * (1.f - lx) * ((vy0 && vx0) ? 1.f : 0.f);
                wg.y = (1.f - ly) * lx         * ((vy0 && vx1) ? 1.f : 0.f);
                wg.z = ly * (1.f - lx)         * ((vy1 && vx0) ? 1.f : 0.f);
                wg.w = ly * lx                 * ((vy1 && vx1) ? 1.f : 0.f);
                int y0c = min(max(y0, 0), H_ - 1), y1c = min(max(y1, 0), H_ - 1);
                int x0c = min(max(x0, 0), W_ - 1), x1c = min(max(x1, 0), W_ - 1);
                int4 ix;
                ix.x = y0c * W_ + x0c; ix.y = y0c * W_ + x1c;
                ix.z = y1c * W_ + x0c; ix.w = y1c * W_ + x1c;
                pwb[prv * 128 + px] = wg;
                pib[prv * 128 + px] = ix;
            }
        }

        // ---- interleaved gather(it) + mma(it-1) ----
#pragma unroll
        for (int i = 0; i < 8; ++i) {
            if (it < 9) {
                int px = i * 16 + (wid << 1) + half;
                float4 wg = pwb[cur * 128 + px];
                int4   ix = pib[cur * 128 + px];
                ulonglong2 a4 = *(const ulonglong2*)(xt + (size_t)ix.x * C_ + cs);
                ulonglong2 b4 = *(const ulonglong2*)(xt + (size_t)ix.y * C_ + cs);
                ulonglong2 c4 = *(const ulonglong2*)(xt + (size_t)ix.z * C_ + cs);
                ulonglong2 d4 = *(const ulonglong2*)(xt + (size_t)ix.w * C_ + cs);
                unsigned long long w00p = pk2(wg.x, wg.x);
                unsigned long long w01p = pk2(wg.y, wg.y);
                unsigned long long w10p = pk2(wg.z, wg.z);
                unsigned long long w11p = pk2(wg.w, wg.w);
                unsigned long long lo = fma2(w00p, a4.x,
                                        fma2(w01p, b4.x,
                                        fma2(w10p, c4.x,
                                        fma2(w11p, d4.x, 0ULL))));
                unsigned long long hi = fma2(w00p, a4.y,
                                        fma2(w01p, b4.y,
                                        fma2(w10p, c4.y,
                                        fma2(w11p, d4.y, 0ULL))));
                float2 flo = upk(lo), fhi = upk(hi);
                uint4 u;
                u.x = to_tf32(flo.x); u.y = to_tf32(flo.y);
                u.z = to_tf32(fhi.x); u.w = to_tf32(fhi.y);
                *(uint4*)(vcur + px * VP + cs) = u;
            }
            if (it > 0) {
                int k0 = i * 8;
                uint32_t a0 = vprv[(warp_m + g)     * VP + k0 + tg];
                uint32_t a1 = vprv[(warp_m + g + 8) * VP + k0 + tg];
                uint32_t a2 = vprv[(warp_m + g)     * VP + k0 + tg + 4];
                uint32_t a3 = vprv[(warp_m + g + 8) * VP + k0 + tg + 4];
#pragma unroll
                for (int nb = 0; nb < 8; ++nb) {
                    uint32_t b0 = wprv[(k0 + tg)     * WP + nb * 8 + g];
                    uint32_t b1 = wprv[(k0 + tg + 4) * WP + nb * 8 + g];
                    mma_tf32(acc[nb], a0, a1, a2, a3, b0, b1);
                }
            }
        }
        __syncthreads();
    }

    // ---- epilogue ----
    int p = warp_m + g;
    float* outb = out + (((size_t)b * COUT_) * H_ + h) * W_;
#pragma unroll
    for (int nb = 0; nb < 8; ++nb) {
        int o = nb * 8 + tg * 2;
        outb[(size_t)o       * HW_ + p]     = acc[nb][0];
        outb[(size_t)(o + 1) * HW_ + p]     = acc[nb][1];
        outb[(size_t)o       * HW_ + p + 8] = acc[nb][2];
        outb[(size_t)(o + 1) * HW_ + p + 8] = acc[nb][3];
    }
}

// ---------------------------------------------------------------------------
extern "C" void kernel_launch(void* const* d_in, const int* in_sizes, int n_in,
                              void* d_out, int out_size) {
    const float* x        = (const float*)d_in[0];
    const float* w_offset = (const float*)d_in[1];
    const float* w_deform = (const float*)d_in[2];
    float* out = (float*)d_out;

    cudaFuncSetAttribute(k_deform_mma,
                         cudaFuncAttributeMaxDynamicSharedMemorySize, DSM_BYTES);
    cudaFuncSetAttribute(k_offset_mma,
                         cudaFuncAttributeMaxDynamicSharedMemorySize, OSM_WORDS * 4);

    k_transpose_w<<<(K2_ * C_ * COUT_ + 255) / 256, 256>>>(w_deform);
    k_transpose_wo<<<(3 * 192 * 24 + 255) / 256, 256>>>(w_offset);
    k_transpose_x<<<B_ * H_, 256>>>(x);
    k_offset_mma<<<B_ * H_, 256, OSM_WORDS * 4>>>(nullptr);
    k_deform_mma<<<B_ * H_, 256, DSM_BYTES>>>(out);
}